// round 1
// baseline (speedup 1.0000x reference)
#include <cuda_runtime.h>
#include <math.h>

#define Bz 8
#define Tz 16
#define Sz 400
#define Hz 512
#define Cz 512
#define Ez 128
#define Vz 50000
#define OOVz 50
#define VEz 50050

// Output layout: tuple flattened in order
#define OUT_FVD  0
#define OUT_CTX  (Bz*Tz*VEz)
#define OUT_H    (OUT_CTX + Bz*Cz)
#define OUT_C    (OUT_H + Bz*Hz)
#define OUT_ATTN (OUT_C + Bz*Hz)
#define OUT_PGEN (OUT_ATTN + Bz*Tz*Sz)
#define OUT_COV  (OUT_PGEN + Bz)

// ---- device scratch (allocation-free: __device__ globals) ----
__device__ float g_wt[(size_t)Hz*Vz];      // vocab_w transposed [k][j]  (102.4 MB)
__device__ float g_encp[Bz*Sz*Hz];         // enc_proj + energy_b        (6.55 MB)
__device__ float g_h[Bz*Hz], g_c[Bz*Hz], g_ctx[Bz*Cz], g_cov[Bz*Sz];
__device__ float g_x[Bz*Ez];
__device__ float g_gates[Bz*4*Hz];
__device__ float g_hp[Bz*Hz];
__device__ float g_e[Bz*Sz];
__device__ float g_probs[Bz*Sz];
__device__ float g_attnd[Bz*Hz];
__device__ float g_pgen[Bz];
__device__ float g_ssum[Bz];
__device__ float g_logits[(size_t)Bz*Vz];  // 1.6 MB

__device__ __forceinline__ float sigmoidf_(float x){ return 1.f/(1.f+expf(-x)); }

// ---- init recurrent state from inputs ----
__global__ void k_init(const float* __restrict__ h0, const float* __restrict__ c0,
                       const float* __restrict__ ctx, const float* __restrict__ cov){
    int i = blockIdx.x*blockDim.x + threadIdx.x;
    if (i < Bz*Hz){ g_h[i] = h0[i]; g_c[i] = c0[i]; }
    if (i < Bz*Cz)  g_ctx[i] = ctx[i];
    if (i < Bz*Sz)  g_cov[i] = cov[i];
}

// ---- transpose vocab_w (V x H) -> g_wt (H x V) ----
__global__ void k_transpose(const float* __restrict__ w){
    __shared__ float tile[32][33];
    int jb = blockIdx.x*32, kb = blockIdx.y*32;
#pragma unroll
    for (int r = 0; r < 32; r += 8){
        int jj = jb + threadIdx.y + r;
        if (jj < Vz) tile[threadIdx.y + r][threadIdx.x] = w[(size_t)jj*Hz + kb + threadIdx.x];
    }
    __syncthreads();
#pragma unroll
    for (int r = 0; r < 32; r += 8){
        int kk = kb + threadIdx.y + r;
        int jj = jb + threadIdx.x;
        if (jj < Vz) g_wt[(size_t)kk*Vz + jj] = tile[threadIdx.x][threadIdx.y + r];
    }
}

// ---- enc_proj GEMM: C[3200,512] = enc[3200,512] * ew[:,H:]^T + eb ----
// Register-blocked: BM=128, BN=64, BK=16, thread tile 8x4, 256 threads.
__global__ __launch_bounds__(256) void k_encproj(const float* __restrict__ enc,
                                                 const float* __restrict__ ew,
                                                 const float* __restrict__ eb){
    __shared__ float As[16][128];
    __shared__ float Bs[16][64];
    int tid = threadIdx.x;
    int bm = blockIdx.x * 128;
    int bn = blockIdx.y * 64;
    float acc[8][4] = {};
    for (int k0 = 0; k0 < 512; k0 += 16){
#pragma unroll
        for (int r = 0; r < 2; r++){
            int id = tid + r*256;        // 0..511 float4 slots
            int m  = id >> 2;
            int kq = (id & 3) * 4;
            float4 v = *(const float4*)(enc + (size_t)(bm+m)*512 + k0 + kq);
            As[kq  ][m] = v.x; As[kq+1][m] = v.y; As[kq+2][m] = v.z; As[kq+3][m] = v.w;
        }
        {
            int n  = tid >> 2;
            int kq = (tid & 3) * 4;
            float4 v = *(const float4*)(ew + (size_t)(bn+n)*1024 + 512 + k0 + kq);
            Bs[kq  ][n] = v.x; Bs[kq+1][n] = v.y; Bs[kq+2][n] = v.z; Bs[kq+3][n] = v.w;
        }
        __syncthreads();
        int tm = (tid >> 4) * 8, tn = (tid & 15) * 4;
#pragma unroll
        for (int kk = 0; kk < 16; kk++){
            float a[8], bb[4];
            *(float4*)&a[0] = *(const float4*)&As[kk][tm];
            *(float4*)&a[4] = *(const float4*)&As[kk][tm+4];
            *(float4*)&bb[0] = *(const float4*)&Bs[kk][tn];
#pragma unroll
            for (int i = 0; i < 8; i++)
#pragma unroll
                for (int j = 0; j < 4; j++) acc[i][j] += a[i]*bb[j];
        }
        __syncthreads();
    }
    int tm = (tid >> 4) * 8, tn = (tid & 15) * 4;
#pragma unroll
    for (int i = 0; i < 8; i++)
#pragma unroll
        for (int j = 0; j < 4; j++)
            g_encp[(size_t)(bm+tm+i)*512 + bn+tn+j] = acc[i][j] + eb[bn+tn+j];
}

// ---- x for t=0: x[b] = [emb(b,0), ctx(b)] @ xctx_w^T + xctx_b ----
__global__ void k_x0(const float* __restrict__ emb, const float* __restrict__ xw,
                     const float* __restrict__ xb){
    int b = blockIdx.x, j = threadIdx.x;   // 128 threads
    __shared__ float se[Ez];
    __shared__ float sc[Cz];
    se[j] = emb[(size_t)b*Tz*Ez + j];
    for (int k = j; k < Cz; k += Ez) sc[k] = g_ctx[b*Cz + k];
    __syncthreads();
    const float4* w4 = (const float4*)(xw + (size_t)j*640);
    const float4* e4 = (const float4*)se;
    const float4* c4 = (const float4*)sc;
    float a = xb[j];
#pragma unroll 8
    for (int kk = 0; kk < 32; kk++){ float4 w = w4[kk],      v = e4[kk]; a += w.x*v.x+w.y*v.y+w.z*v.z+w.w*v.w; }
#pragma unroll 8
    for (int kk = 0; kk < 128; kk++){ float4 w = w4[32+kk],  v = c4[kk]; a += w.x*v.x+w.y*v.y+w.z*v.z+w.w*v.w; }
    g_x[b*Ez + j] = a;
}

// ---- gates: warp per row j (2048 rows), 8 batches per warp ----
__global__ __launch_bounds__(256) void k_gates(const float* __restrict__ Wih,
                                               const float* __restrict__ Whh,
                                               const float* __restrict__ bih,
                                               const float* __restrict__ bhh){
    __shared__ float sx[Bz*Ez];
    __shared__ float sh[Bz*Hz];
    int tid = threadIdx.x;
    for (int i = tid; i < Bz*Ez; i += 256) sx[i] = g_x[i];
    for (int i = tid; i < Bz*Hz; i += 256) sh[i] = g_h[i];
    __syncthreads();
    int warp = tid >> 5, lane = tid & 31;
    int j = blockIdx.x*8 + warp;
    float acc[Bz] = {0,0,0,0,0,0,0,0};
    const float* wi = Wih + (size_t)j*Ez;
#pragma unroll
    for (int i = 0; i < 4; i++){
        int k = lane + 32*i; float w = wi[k];
#pragma unroll
        for (int b = 0; b < Bz; b++) acc[b] += w * sx[b*Ez + k];
    }
    const float* wh = Whh + (size_t)j*Hz;
#pragma unroll
    for (int i = 0; i < 16; i++){
        int k = lane + 32*i; float w = wh[k];
#pragma unroll
        for (int b = 0; b < Bz; b++) acc[b] += w * sh[b*Hz + k];
    }
#pragma unroll
    for (int off = 16; off; off >>= 1)
#pragma unroll
        for (int b = 0; b < Bz; b++) acc[b] += __shfl_xor_sync(0xffffffffu, acc[b], off);
    if (lane < Bz) g_gates[lane*4*Hz + j] = acc[lane] + bih[j] + bhh[j];
}

// ---- LSTM elementwise + h_proj (h_new @ energy_w[:, :H]^T) ----
__global__ __launch_bounds__(512) void k_lstm(const float* __restrict__ ew){
    int b = blockIdx.x, j = threadIdx.x;
    __shared__ float hs[Hz];
    const float* gb = g_gates + b*4*Hz;
    float gi = gb[j], gf = gb[Hz+j], gg = gb[2*Hz+j], go = gb[3*Hz+j];
    float cn = sigmoidf_(gf)*g_c[b*Hz+j] + sigmoidf_(gi)*tanhf(gg);
    g_c[b*Hz+j] = cn;
    float hn = sigmoidf_(go)*tanhf(cn);
    g_h[b*Hz+j] = hn;
    hs[j] = hn;
    __syncthreads();
    const float4* w4 = (const float4*)(ew + (size_t)j*1024);
    const float4* h4 = (const float4*)hs;
    float a0=0.f, a1=0.f, a2=0.f, a3=0.f;
#pragma unroll 4
    for (int kk = 0; kk < 128; kk += 4){
        float4 w, h;
        w = w4[kk  ]; h = h4[kk  ]; a0 += w.x*h.x+w.y*h.y+w.z*h.z+w.w*h.w;
        w = w4[kk+1]; h = h4[kk+1]; a1 += w.x*h.x+w.y*h.y+w.z*h.z+w.w*h.w;
        w = w4[kk+2]; h = h4[kk+2]; a2 += w.x*h.x+w.y*h.y+w.z*h.z+w.w*h.w;
        w = w4[kk+3]; h = h4[kk+3]; a3 += w.x*h.x+w.y*h.y+w.z*h.z+w.w*h.w;
    }
    g_hp[b*Hz+j] = a0+a1+a2+a3;
}

// ---- attention energies: e[b,s] = v . tanh(hp + enc_proj + cov*cov_w) ----
__global__ __launch_bounds__(256) void k_energy(const float* __restrict__ covw,
                                                const float* __restrict__ vv){
    int b = blockIdx.y, tid = threadIdx.x;
    __shared__ float hp[Hz], cw[Hz], sv[Hz];
    for (int i = tid; i < Hz; i += 256){ hp[i] = g_hp[b*Hz+i]; cw[i] = covw[i]; sv[i] = vv[i]; }
    __syncthreads();
    int warp = tid >> 5, lane = tid & 31;
    int s = blockIdx.x*8 + warp;
    float cb = g_cov[b*Sz + s];
    const float* ep = g_encp + ((size_t)(b*Sz+s))*Hz;
    float acc = 0.f;
#pragma unroll
    for (int i = 0; i < 16; i++){
        int k = lane + 32*i;
        float val = hp[k] + ep[k] + cb*cw[k];
        acc += sv[k]*tanhf(val);
    }
#pragma unroll
    for (int off = 16; off; off >>= 1) acc += __shfl_xor_sync(0xffffffffu, acc, off);
    if (lane == 0) g_e[b*Sz + s] = acc;
}

// ---- fused per-batch: softmax + ctx + coverage + p_gen + attnd + x_{t+1} ----
__global__ __launch_bounds__(512) void k_attn(const float* __restrict__ enc,
                                              const float* __restrict__ mask,
                                              const float* __restrict__ pw, const float* __restrict__ pb,
                                              const float* __restrict__ aw, const float* __restrict__ ab,
                                              const float* __restrict__ xw, const float* __restrict__ xb,
                                              const float* __restrict__ emb,
                                              float* __restrict__ out_attn,
                                              float* __restrict__ out_cov,
                                              float* __restrict__ out_pgen,
                                              int t){
    int b = blockIdx.x, tid = threadIdx.x;
    __shared__ float p[Sz];
    __shared__ float hs[Hz];
    __shared__ float cs[Cz];
    __shared__ float red[512];
    hs[tid] = g_h[b*Hz + tid];

    float e  = (tid < Sz) ? g_e[b*Sz + tid] : -1e30f;
    red[tid] = e; __syncthreads();
    for (int s = 256; s > 0; s >>= 1){ if (tid < s) red[tid] = fmaxf(red[tid], red[tid+s]); __syncthreads(); }
    float m = red[0]; __syncthreads();

    float ex = (tid < Sz) ? expf(e - m) : 0.f;
    red[tid] = ex; __syncthreads();
    for (int s = 256; s > 0; s >>= 1){ if (tid < s) red[tid] += red[tid+s]; __syncthreads(); }
    float s1 = red[0]; __syncthreads();

    float pm = (tid < Sz) ? (ex/s1) * mask[b*Sz + tid] : 0.f;
    red[tid] = pm; __syncthreads();
    for (int s = 256; s > 0; s >>= 1){ if (tid < s) red[tid] += red[tid+s]; __syncthreads(); }
    float s2 = red[0]; __syncthreads();

    float pr = pm / (s2 + 1e-12f);
    if (tid < Sz){
        p[tid] = pr;
        g_probs[b*Sz + tid] = pr;
        out_attn[((size_t)b*Tz + t)*Sz + tid] = pr;
        float cn = g_cov[b*Sz + tid] + pr;
        g_cov[b*Sz + tid] = cn;
        out_cov[((size_t)b*Tz + t)*Sz + tid] = cn;
    }
    __syncthreads();

    // ctx_new[h] = sum_s p[s] * enc[b,s,h]
    {
        const float* eo = enc + (size_t)b*Sz*Cz + tid;
        float acc = 0.f;
#pragma unroll 8
        for (int s = 0; s < Sz; s++) acc += p[s] * eo[(size_t)s*Cz];
        cs[tid] = acc;
        g_ctx[b*Cz + tid] = acc;
    }
    __syncthreads();

    // p_gen = sigmoid(pw . [ctx, h, x] + pb)
    {
        float z = cs[tid]*pw[tid] + hs[tid]*pw[512 + tid];
        if (tid < Ez) z += g_x[b*Ez + tid]*pw[1024 + tid];
        red[tid] = z; __syncthreads();
        for (int s = 256; s > 0; s >>= 1){ if (tid < s) red[tid] += red[tid+s]; __syncthreads(); }
        if (tid == 0){
            float pg = sigmoidf_(red[0] + pb[0]);
            g_pgen[b] = pg;
            if (t == Tz-1) out_pgen[b] = pg;
        }
        __syncthreads();
    }

    // attnd[hh] = attnd_b + [h, ctx] . attnd_w row
    {
        const float4* w4 = (const float4*)(aw + (size_t)tid*1024);
        const float4* h4 = (const float4*)hs;
        const float4* c4 = (const float4*)cs;
        float a0 = 0.f, a1 = 0.f;
#pragma unroll 4
        for (int kk = 0; kk < 128; kk++){ float4 w = w4[kk],     h = h4[kk]; a0 += w.x*h.x+w.y*h.y+w.z*h.z+w.w*h.w; }
#pragma unroll 4
        for (int kk = 0; kk < 128; kk++){ float4 w = w4[128+kk], h = c4[kk]; a1 += w.x*h.x+w.y*h.y+w.z*h.z+w.w*h.w; }
        g_attnd[b*Hz + tid] = a0 + a1 + ab[tid];
    }

    // x for next step (uses ctx_new and emb[:, t+1])
    if (t+1 < Tz && tid < Ez){
        const float4* w4 = (const float4*)(xw + (size_t)tid*640);
        const float4* e4 = (const float4*)(emb + ((size_t)b*Tz + (t+1))*Ez);
        const float4* c4 = (const float4*)cs;
        float a = xb[tid];
#pragma unroll 8
        for (int kk = 0; kk < 32; kk++){ float4 w = w4[kk],    v = e4[kk]; a += w.x*v.x+w.y*v.y+w.z*v.z+w.w*v.w; }
#pragma unroll 8
        for (int kk = 0; kk < 128; kk++){ float4 w = w4[32+kk], v = c4[kk]; a += w.x*v.x+w.y*v.y+w.z*v.z+w.w*v.w; }
        g_x[b*Ez + tid] = a;
    }
}

// ---- vocab GEMV: logits[b,j] = vb[j] + attnd[b,:] . Wt[:,j], thread per column j ----
__global__ __launch_bounds__(256) void k_vocab(const float* __restrict__ vb){
    __shared__ float4 a4[Bz][Hz/4];
    int tid = threadIdx.x;
    const float4* src = (const float4*)g_attnd;
#pragma unroll
    for (int r = 0; r < 4; r++) ((float4*)a4)[tid + r*256] = src[tid + r*256];
    __syncthreads();
    int j = blockIdx.x*256 + tid;
    if (j >= Vz) return;
    float bj = vb[j];
    float acc[Bz];
#pragma unroll
    for (int b = 0; b < Bz; b++) acc[b] = bj;
    const float* wp = g_wt + j;
#pragma unroll 2
    for (int kk = 0; kk < 128; kk++){
        float w0 = wp[0], w1 = wp[Vz], w2 = wp[2*(size_t)Vz], w3 = wp[3*(size_t)Vz];
        wp += 4*(size_t)Vz;
#pragma unroll
        for (int b = 0; b < Bz; b++){
            float4 a = a4[b][kk];
            acc[b] += w0*a.x + w1*a.y + w2*a.z + w3*a.w;
        }
    }
#pragma unroll
    for (int b = 0; b < Bz; b++) g_logits[(size_t)b*Vz + j] = acc[b];
}

// ---- vocab softmax reduce (exp in place, sum per batch) ----
__global__ __launch_bounds__(1024) void k_vsoftmax(){
    int b = blockIdx.x, tid = threadIdx.x;
    __shared__ float red[1024];
    float* l = g_logits + (size_t)b*Vz;
    float m = -1e30f;
    for (int i = tid; i < Vz; i += 1024) m = fmaxf(m, l[i]);
    red[tid] = m; __syncthreads();
    for (int s = 512; s > 0; s >>= 1){ if (tid < s) red[tid] = fmaxf(red[tid], red[tid+s]); __syncthreads(); }
    m = red[0]; __syncthreads();
    float sum = 0.f;
    for (int i = tid; i < Vz; i += 1024){ float e = expf(l[i] - m); l[i] = e; sum += e; }
    red[tid] = sum; __syncthreads();
    for (int s = 512; s > 0; s >>= 1){ if (tid < s) red[tid] += red[tid+s]; __syncthreads(); }
    if (tid == 0) g_ssum[b] = red[0];
}

// ---- write final dist (base: p_gen * vocab_dist, zeros in OOV region) ----
__global__ void k_final(float* __restrict__ out, int t){
    int i = blockIdx.x*256 + threadIdx.x;
    if (i >= Bz*VEz) return;
    int b = i / VEz, j = i - b*VEz;
    float val = 0.f;
    if (j < Vz) val = g_logits[(size_t)b*Vz + j] * (g_pgen[b] / g_ssum[b]);
    out[((size_t)b*Tz + t)*VEz + j] = val;
}

// ---- scatter copy probs into final dist ----
__global__ void k_scatter(float* __restrict__ out, const int* __restrict__ idx, int t){
    int i = blockIdx.x*256 + threadIdx.x;
    if (i >= Bz*Sz) return;
    int b = i / Sz;
    float add = (1.f - g_pgen[b]) * g_probs[i];
    int j = idx[i];
    atomicAdd(out + ((size_t)b*Tz + t)*VEz + j, add);
}

// ---- final state outputs ----
__global__ void k_fin(float* __restrict__ out){
    int i = blockIdx.x*256 + threadIdx.x;
    if (i < Bz*Cz) out[OUT_CTX + i] = g_ctx[i];
    if (i < Bz*Hz){ out[OUT_H + i] = g_h[i]; out[OUT_C + i] = g_c[i]; }
}

extern "C" void kernel_launch(void* const* d_in, const int* in_sizes, int n_in,
                              void* d_out, int out_size){
    const float* emb   = (const float*)d_in[0];
    const float* ctx0  = (const float*)d_in[1];
    const float* h0    = (const float*)d_in[2];
    const float* c0    = (const float*)d_in[3];
    const float* enc   = (const float*)d_in[4];
    const float* mask  = (const float*)d_in[5];
    /* extra_zeros d_in[6] unused (zeros) */
    const int*   sidx  = (const int*)  d_in[7];
    const float* cov0  = (const float*)d_in[8];
    const float* Wih   = (const float*)d_in[9];
    const float* Whh   = (const float*)d_in[10];
    const float* bih   = (const float*)d_in[11];
    const float* bhh   = (const float*)d_in[12];
    const float* covw  = (const float*)d_in[13];
    const float* ew    = (const float*)d_in[14];
    const float* eb    = (const float*)d_in[15];
    const float* vvec  = (const float*)d_in[16];
    const float* xw    = (const float*)d_in[17];
    const float* xb    = (const float*)d_in[18];
    const float* aw    = (const float*)d_in[19];
    const float* ab    = (const float*)d_in[20];
    const float* vw    = (const float*)d_in[21];
    const float* vb    = (const float*)d_in[22];
    const float* pw    = (const float*)d_in[23];
    const float* pb    = (const float*)d_in[24];
    float* out = (float*)d_out;

    // Precompute phase
    k_init<<<32, 512>>>(h0, c0, ctx0, cov0);
    k_transpose<<<dim3((Vz+31)/32, Hz/32), dim3(32, 8)>>>(vw);
    k_encproj<<<dim3((Bz*Sz)/128, Hz/64), 256>>>(enc, ew, eb);
    k_x0<<<Bz, Ez>>>(emb, xw, xb);

    for (int t = 0; t < Tz; t++){
        k_gates<<<(4*Hz)/8, 256>>>(Wih, Whh, bih, bhh);
        k_lstm<<<Bz, Hz>>>(ew);
        k_energy<<<dim3(Sz/8, Bz), 256>>>(covw, vvec);
        k_attn<<<Bz, 512>>>(enc, mask, pw, pb, aw, ab, xw, xb, emb,
                            out + OUT_ATTN, out + OUT_COV, out + OUT_PGEN, t);
        k_vocab<<<(Vz + 255)/256, 256>>>(vb);
        k_vsoftmax<<<Bz, 1024>>>();
        k_final<<<(Bz*VEz + 255)/256, 256>>>(out, t);
        k_scatter<<<(Bz*Sz + 255)/256, 256>>>(out, sidx, t);
    }
    k_fin<<<16, 256>>>(out);
}

// round 2
// speedup vs baseline: 1.7859x; 1.7859x over previous
#include <cuda_runtime.h>
#include <math.h>

#define Bz 8
#define Tz 16
#define Sz 400
#define Hz 512
#define Cz 512
#define Ez 128
#define Vz 50000
#define OOVz 50
#define VEz 50050

// Output layout: tuple flattened in order
#define OUT_FVD  0
#define OUT_CTX  (Bz*Tz*VEz)
#define OUT_H    (OUT_CTX + Bz*Cz)
#define OUT_C    (OUT_H + Bz*Hz)
#define OUT_ATTN (OUT_C + Bz*Hz)
#define OUT_PGEN (OUT_ATTN + Bz*Tz*Sz)
#define OUT_COV  (OUT_PGEN + Bz)

// ---- device scratch ----
__device__ float g_wt[(size_t)Hz*Vz];      // vocab_w transposed [k][j]
__device__ float g_encp[Bz*Sz*Hz];         // enc_proj + energy_b
__device__ float g_h[Bz*Hz];
__device__ float g_c2[2][Bz*Hz];           // c ping-pong
__device__ float g_x2[2][Bz*Ez];           // x ping-pong
__device__ float g_ctx[Bz*Cz];
__device__ float g_cov[Bz*Sz];
__device__ float g_gates[Bz*4*Hz];
__device__ float g_hp[Bz*Hz];
__device__ float g_e[Bz*Sz];
__device__ float g_probs[Bz*Sz];
__device__ float g_attnd[Bz*Hz];
__device__ float g_pgen[Bz];
__device__ float g_max[Bz];
__device__ float g_scale[Bz];
__device__ float g_logits[(size_t)Bz*Vz];

__device__ __forceinline__ float sigmoidf_(float x){ return 1.f/(1.f+expf(-x)); }

// ---- init recurrent state ----
__global__ void k_init(const float* __restrict__ h0, const float* __restrict__ c0,
                       const float* __restrict__ ctx, const float* __restrict__ cov){
    int i = blockIdx.x*blockDim.x + threadIdx.x;
    if (i < Bz*Hz){ g_h[i] = h0[i]; g_c2[0][i] = c0[i]; }
    if (i < Bz*Cz)  g_ctx[i] = ctx[i];
    if (i < Bz*Sz)  g_cov[i] = cov[i];
}

// ---- zero the final-vocab-dist region (enables order-free atomic writes) ----
__global__ void k_zero(float* __restrict__ out){
    size_t i = (size_t)blockIdx.x*256 + threadIdx.x;
    if (i < (size_t)Bz*Tz*VEz/4) ((float4*)out)[i] = make_float4(0.f,0.f,0.f,0.f);
}

// ---- transpose vocab_w (V x H) -> g_wt (H x V) ----
__global__ void k_transpose(const float* __restrict__ w){
    __shared__ float tile[32][33];
    int jb = blockIdx.x*32, kb = blockIdx.y*32;
#pragma unroll
    for (int r = 0; r < 32; r += 8){
        int jj = jb + threadIdx.y + r;
        if (jj < Vz) tile[threadIdx.y + r][threadIdx.x] = w[(size_t)jj*Hz + kb + threadIdx.x];
    }
    __syncthreads();
#pragma unroll
    for (int r = 0; r < 32; r += 8){
        int kk = kb + threadIdx.y + r;
        int jj = jb + threadIdx.x;
        if (jj < Vz) g_wt[(size_t)kk*Vz + jj] = tile[threadIdx.x][threadIdx.y + r];
    }
}

// ---- enc_proj GEMM: [3200,512] = enc[3200,512] * ew[:,H:]^T + eb ----
__global__ __launch_bounds__(256) void k_encproj(const float* __restrict__ enc,
                                                 const float* __restrict__ ew,
                                                 const float* __restrict__ eb){
    __shared__ float As[16][128];
    __shared__ float Bs[16][64];
    int tid = threadIdx.x;
    int bm = blockIdx.x * 128;
    int bn = blockIdx.y * 64;
    float acc[8][4] = {};
    for (int k0 = 0; k0 < 512; k0 += 16){
#pragma unroll
        for (int r = 0; r < 2; r++){
            int id = tid + r*256;
            int m  = id >> 2;
            int kq = (id & 3) * 4;
            float4 v = *(const float4*)(enc + (size_t)(bm+m)*512 + k0 + kq);
            As[kq  ][m] = v.x; As[kq+1][m] = v.y; As[kq+2][m] = v.z; As[kq+3][m] = v.w;
        }
        {
            int n  = tid >> 2;
            int kq = (tid & 3) * 4;
            float4 v = *(const float4*)(ew + (size_t)(bn+n)*1024 + 512 + k0 + kq);
            Bs[kq  ][n] = v.x; Bs[kq+1][n] = v.y; Bs[kq+2][n] = v.z; Bs[kq+3][n] = v.w;
        }
        __syncthreads();
        int tm = (tid >> 4) * 8, tn = (tid & 15) * 4;
#pragma unroll
        for (int kk = 0; kk < 16; kk++){
            float a[8], bb[4];
            *(float4*)&a[0] = *(const float4*)&As[kk][tm];
            *(float4*)&a[4] = *(const float4*)&As[kk][tm+4];
            *(float4*)&bb[0] = *(const float4*)&Bs[kk][tn];
#pragma unroll
            for (int i = 0; i < 8; i++)
#pragma unroll
                for (int j = 0; j < 4; j++) acc[i][j] += a[i]*bb[j];
        }
        __syncthreads();
    }
    int tm = (tid >> 4) * 8, tn = (tid & 15) * 4;
#pragma unroll
    for (int i = 0; i < 8; i++)
#pragma unroll
        for (int j = 0; j < 4; j++)
            g_encp[(size_t)(bm+tm+i)*512 + bn+tn+j] = acc[i][j] + eb[bn+tn+j];
}

// ---- x for t=0: warp-per-row, 32 blocks ----
__global__ __launch_bounds__(256) void k_x0(const float* __restrict__ emb,
                                            const float* __restrict__ xw,
                                            const float* __restrict__ xb){
    // grid 32 blocks: b = blockIdx.x/4; rows = (blockIdx.x%4)*32 + warp*4 + q
    int b = blockIdx.x >> 2;
    int tid = threadIdx.x, warp = tid >> 5, lane = tid & 31;
    __shared__ float vec[640];  // [emb(b,0), ctx(b)]
    for (int i = tid; i < 128; i += 256) vec[i] = emb[(size_t)b*Tz*Ez + i];
    for (int i = tid; i < 512; i += 256) vec[128 + i] = g_ctx[b*Cz + i];
    __syncthreads();
#pragma unroll
    for (int q = 0; q < 4; q++){
        int j = (blockIdx.x & 3)*32 + warp*4 + q;
        const float* w = xw + (size_t)j*640;
        float acc = 0.f;
#pragma unroll
        for (int i = 0; i < 20; i++){
            int k = lane + 32*i;
            acc += w[k]*vec[k];
        }
#pragma unroll
        for (int off = 16; off; off >>= 1) acc += __shfl_xor_sync(0xffffffffu, acc, off);
        if (lane == 0) g_x2[0][b*Ez + j] = acc + xb[j];
    }
}

// ---- gates: warp per row j, 8 batches per warp; 256 blocks ----
__global__ __launch_bounds__(256) void k_gates(const float* __restrict__ Wih,
                                               const float* __restrict__ Whh,
                                               const float* __restrict__ bih,
                                               const float* __restrict__ bhh,
                                               const float* __restrict__ x){
    __shared__ float sx[Bz*Ez];
    __shared__ float sh[Bz*Hz];
    int tid = threadIdx.x;
    for (int i = tid; i < Bz*Ez; i += 256) sx[i] = x[i];
    for (int i = tid; i < Bz*Hz; i += 256) sh[i] = g_h[i];
    __syncthreads();
    int warp = tid >> 5, lane = tid & 31;
    int j = blockIdx.x*8 + warp;
    float acc[Bz] = {0,0,0,0,0,0,0,0};
    const float* wi = Wih + (size_t)j*Ez;
#pragma unroll
    for (int i = 0; i < 4; i++){
        int k = lane + 32*i; float w = wi[k];
#pragma unroll
        for (int b = 0; b < Bz; b++) acc[b] += w * sx[b*Ez + k];
    }
    const float* wh = Whh + (size_t)j*Hz;
#pragma unroll
    for (int i = 0; i < 16; i++){
        int k = lane + 32*i; float w = wh[k];
#pragma unroll
        for (int b = 0; b < Bz; b++) acc[b] += w * sh[b*Hz + k];
    }
#pragma unroll
    for (int off = 16; off; off >>= 1)
#pragma unroll
        for (int b = 0; b < Bz; b++) acc[b] += __shfl_xor_sync(0xffffffffu, acc[b], off);
    if (lane < Bz) g_gates[lane*4*Hz + j] = acc[lane] + bih[j] + bhh[j];
}

// ---- fused LSTM elementwise + h_proj; grid (4, Bz), 512 thr ----
__global__ __launch_bounds__(512) void k_lstmhp(const float* __restrict__ ew,
                                                const float* __restrict__ cin,
                                                float* __restrict__ cout){
    int b = blockIdx.y, tid = threadIdx.x;
    __shared__ float hs[Hz];
    // phase 1: every block computes h_new redundantly (reads are race-free: cin != cout)
    {
        const float* gb = g_gates + b*4*Hz;
        float gi = gb[tid], gf = gb[Hz+tid], gg = gb[2*Hz+tid], go = gb[3*Hz+tid];
        float cn = sigmoidf_(gf)*cin[b*Hz+tid] + sigmoidf_(gi)*tanhf(gg);
        float hn = sigmoidf_(go)*tanhf(cn);
        hs[tid] = hn;
        if (blockIdx.x == 0){ cout[b*Hz+tid] = cn; g_h[b*Hz+tid] = hn; }
    }
    __syncthreads();
    // phase 2: hp rows; 16 warps x 8 rows
    int warp = tid >> 5, lane = tid & 31;
    int r0 = blockIdx.x*128 + warp*8;
#pragma unroll
    for (int q = 0; q < 8; q++){
        int jj = r0 + q;
        const float* w = ew + (size_t)jj*1024;   // first H cols of energy_w row
        float acc = 0.f;
#pragma unroll
        for (int i = 0; i < 16; i++){
            int k = lane + 32*i;
            acc += w[k]*hs[k];
        }
#pragma unroll
        for (int off = 16; off; off >>= 1) acc += __shfl_xor_sync(0xffffffffu, acc, off);
        if (lane == 0) g_hp[b*Hz + jj] = acc;
    }
}

// ---- attention energies: warp-per-s; grid (50, Bz) ----
__global__ __launch_bounds__(256) void k_energy(const float* __restrict__ covw,
                                                const float* __restrict__ vv){
    int b = blockIdx.y, tid = threadIdx.x;
    __shared__ float hp[Hz], cw[Hz], sv[Hz];
    for (int i = tid; i < Hz; i += 256){ hp[i] = g_hp[b*Hz+i]; cw[i] = covw[i]; sv[i] = vv[i]; }
    __syncthreads();
    int warp = tid >> 5, lane = tid & 31;
    int s = blockIdx.x*8 + warp;
    float cb = g_cov[b*Sz + s];
    const float* ep = g_encp + ((size_t)(b*Sz+s))*Hz;
    float acc = 0.f;
#pragma unroll
    for (int i = 0; i < 16; i++){
        int k = lane + 32*i;
        acc += sv[k]*tanhf(hp[k] + ep[k] + cb*cw[k]);
    }
#pragma unroll
    for (int off = 16; off; off >>= 1) acc += __shfl_xor_sync(0xffffffffu, acc, off);
    if (lane == 0) g_e[b*Sz + s] = acc;
}

// ---- softmax + coverage + outputs + zero ctx; 8 blocks ----
__global__ __launch_bounds__(512) void k_attn(const float* __restrict__ mask,
                                              float* __restrict__ out_attn,
                                              float* __restrict__ out_cov,
                                              int t){
    int b = blockIdx.x, tid = threadIdx.x;
    __shared__ float red[512];

    float e  = (tid < Sz) ? g_e[b*Sz + tid] : -1e30f;
    red[tid] = e; __syncthreads();
    for (int s = 256; s > 0; s >>= 1){ if (tid < s) red[tid] = fmaxf(red[tid], red[tid+s]); __syncthreads(); }
    float m = red[0]; __syncthreads();

    float ex = (tid < Sz) ? expf(e - m) : 0.f;
    red[tid] = ex; __syncthreads();
    for (int s = 256; s > 0; s >>= 1){ if (tid < s) red[tid] += red[tid+s]; __syncthreads(); }
    float s1 = red[0]; __syncthreads();

    float pm = (tid < Sz) ? (ex/s1) * mask[b*Sz + tid] : 0.f;
    red[tid] = pm; __syncthreads();
    for (int s = 256; s > 0; s >>= 1){ if (tid < s) red[tid] += red[tid+s]; __syncthreads(); }
    float s2 = red[0];

    float pr = pm / (s2 + 1e-12f);
    if (tid < Sz){
        g_probs[b*Sz + tid] = pr;
        out_attn[((size_t)b*Tz + t)*Sz + tid] = pr;
        float cn = g_cov[b*Sz + tid] + pr;
        g_cov[b*Sz + tid] = cn;
        out_cov[((size_t)b*Tz + t)*Sz + tid] = cn;
    }
    g_ctx[b*Cz + tid] = 0.f;   // ready for k_ctx atomics
}

// ---- ctx: grid (8 s-chunks, Bz), 512 thr, atomicAdd partials ----
__global__ __launch_bounds__(512) void k_ctx(const float* __restrict__ enc){
    int b = blockIdx.y, sc = blockIdx.x, tid = threadIdx.x;
    __shared__ float p[50];
    if (tid < 50) p[tid] = g_probs[b*Sz + sc*50 + tid];
    __syncthreads();
    const float* eo = enc + ((size_t)b*Sz + sc*50)*Cz + tid;
    float acc = 0.f;
#pragma unroll 10
    for (int s = 0; s < 50; s++) acc += p[s] * eo[(size_t)s*Cz];
    atomicAdd(&g_ctx[b*Cz + tid], acc);
}

// ---- attnd (warp-per-row) + pgen + x_next; grid 136 blocks ----
__global__ __launch_bounds__(256) void k_attnd(const float* __restrict__ aw, const float* __restrict__ ab,
                                               const float* __restrict__ pw, const float* __restrict__ pb,
                                               const float* __restrict__ xw, const float* __restrict__ xb,
                                               const float* __restrict__ emb,
                                               const float* __restrict__ xcur,
                                               float* __restrict__ xnxt,
                                               float* __restrict__ out_pgen,
                                               int t){
    int tid = threadIdx.x, warp = tid >> 5, lane = tid & 31;
    if (blockIdx.x < 128){
        // attnd rows: b = blockIdx.x/16, 32 rows per block
        int b = blockIdx.x >> 4;
        __shared__ float hc[1024];
        for (int i = tid; i < 512; i += 256) hc[i]       = g_h[b*Hz + i];
        for (int i = tid; i < 512; i += 256) hc[512 + i] = g_ctx[b*Cz + i];
        __syncthreads();
        int r0 = (blockIdx.x & 15)*32 + warp*4;
#pragma unroll
        for (int q = 0; q < 4; q++){
            int j = r0 + q;
            const float* w = aw + (size_t)j*1024;
            float acc = 0.f;
#pragma unroll
            for (int i = 0; i < 32; i++){
                int k = lane + 32*i;
                acc += w[k]*hc[k];
            }
#pragma unroll
            for (int off = 16; off; off >>= 1) acc += __shfl_xor_sync(0xffffffffu, acc, off);
            if (lane == 0) g_attnd[b*Hz + j] = acc + ab[j];
        }
    } else {
        int b = blockIdx.x - 128;
        __shared__ float vec[640];   // [emb(b,t+1), ctx]
        __shared__ float red[256];
        for (int i = tid; i < 512; i += 256) vec[128 + i] = g_ctx[b*Cz + i];
        if (tid < 128 && t+1 < Tz) vec[tid] = emb[((size_t)b*Tz + (t+1))*Ez + tid];
        // pgen partial: [ctx, h, x] . pw
        float z = g_ctx[b*Cz + tid]*pw[tid] + g_ctx[b*Cz + tid + 256]*pw[tid + 256]
                + g_h[b*Hz + tid]*pw[512 + tid] + g_h[b*Hz + tid + 256]*pw[768 + tid];
        if (tid < 128) z += xcur[b*Ez + tid]*pw[1024 + tid];
        red[tid] = z; __syncthreads();
        for (int s = 128; s > 0; s >>= 1){ if (tid < s) red[tid] += red[tid+s]; __syncthreads(); }
        if (tid == 0){
            float pg = sigmoidf_(red[0] + pb[0]);
            g_pgen[b] = pg;
            if (t == Tz-1) out_pgen[b] = pg;
        }
        // x_next: 8 warps x 16 rows
        if (t+1 < Tz){
#pragma unroll
            for (int q = 0; q < 16; q++){
                int j = warp*16 + q;
                const float* w = xw + (size_t)j*640;
                float acc = 0.f;
#pragma unroll
                for (int i = 0; i < 20; i++){
                    int k = lane + 32*i;
                    acc += w[k]*vec[k];
                }
#pragma unroll
                for (int off = 16; off; off >>= 1) acc += __shfl_xor_sync(0xffffffffu, acc, off);
                if (lane == 0) xnxt[b*Ez + j] = acc + xb[j];
            }
        }
    }
}

// ---- vocab GEMV: thread-per-column, coalesced Wt stream ----
__global__ __launch_bounds__(256) void k_vocab(const float* __restrict__ vb){
    __shared__ float4 a4[Bz][Hz/4];
    int tid = threadIdx.x;
    const float4* src = (const float4*)g_attnd;
#pragma unroll
    for (int r = 0; r < 4; r++) ((float4*)a4)[tid + r*256] = src[tid + r*256];
    __syncthreads();
    int j = blockIdx.x*256 + tid;
    if (j >= Vz) return;
    float bj = vb[j];
    float acc[Bz];
#pragma unroll
    for (int b = 0; b < Bz; b++) acc[b] = bj;
    const float* wp = g_wt + j;
#pragma unroll 4
    for (int kk = 0; kk < 128; kk++){
        float w0 = wp[0], w1 = wp[Vz], w2 = wp[2*(size_t)Vz], w3 = wp[3*(size_t)Vz];
        wp += 4*(size_t)Vz;
#pragma unroll
        for (int b = 0; b < Bz; b++){
            float4 a = a4[b][kk];
            acc[b] += w0*a.x + w1*a.y + w2*a.z + w3*a.w;
        }
    }
#pragma unroll
    for (int b = 0; b < Bz; b++) g_logits[(size_t)b*Vz + j] = acc[b];
}

// ---- vocab softmax stats (max & sum only) ----
__global__ __launch_bounds__(1024) void k_vsoftmax(){
    int b = blockIdx.x, tid = threadIdx.x;
    __shared__ float red[1024];
    const float* l = g_logits + (size_t)b*Vz;
    float m = -1e30f;
    for (int i = tid; i < Vz; i += 1024) m = fmaxf(m, l[i]);
    red[tid] = m; __syncthreads();
    for (int s = 512; s > 0; s >>= 1){ if (tid < s) red[tid] = fmaxf(red[tid], red[tid+s]); __syncthreads(); }
    m = red[0]; __syncthreads();
    float sum = 0.f;
    for (int i = tid; i < Vz; i += 1024) sum += expf(l[i] - m);
    red[tid] = sum; __syncthreads();
    for (int s = 512; s > 0; s >>= 1){ if (tid < s) red[tid] += red[tid+s]; __syncthreads(); }
    if (tid == 0){ g_max[b] = m; g_scale[b] = g_pgen[b] / red[0]; }
}

// ---- final dist write + scatter (order-free atomics onto zeroed region) ----
__global__ __launch_bounds__(256) void k_finalsc(float* __restrict__ out,
                                                 const int* __restrict__ idx, int t){
    int b = blockIdx.y, tid = threadIdx.x;
    float* row = out + ((size_t)b*Tz + t)*VEz;
    if (blockIdx.x < 196){
        int j = blockIdx.x*256 + tid;
        if (j < Vz){
            float val = expf(g_logits[(size_t)b*Vz + j] - g_max[b]) * g_scale[b];
            atomicAdd(row + j, val);
        }
    } else {
        float om = 1.f - g_pgen[b];
#pragma unroll
        for (int s = tid; s < Sz; s += 256){
            float add = om * g_probs[b*Sz + s];
            atomicAdd(row + idx[b*Sz + s], add);
        }
    }
}

// ---- final states ----
__global__ void k_fin(float* __restrict__ out){
    int i = blockIdx.x*256 + threadIdx.x;
    if (i < Bz*Cz) out[OUT_CTX + i] = g_ctx[i];
    if (i < Bz*Hz){ out[OUT_H + i] = g_h[i]; out[OUT_C + i] = g_c2[0][i]; }
}

extern "C" void kernel_launch(void* const* d_in, const int* in_sizes, int n_in,
                              void* d_out, int out_size){
    const float* emb   = (const float*)d_in[0];
    const float* ctx0  = (const float*)d_in[1];
    const float* h0    = (const float*)d_in[2];
    const float* c0    = (const float*)d_in[3];
    const float* enc   = (const float*)d_in[4];
    const float* mask  = (const float*)d_in[5];
    const int*   sidx  = (const int*)  d_in[7];
    const float* cov0  = (const float*)d_in[8];
    const float* Wih   = (const float*)d_in[9];
    const float* Whh   = (const float*)d_in[10];
    const float* bih   = (const float*)d_in[11];
    const float* bhh   = (const float*)d_in[12];
    const float* covw  = (const float*)d_in[13];
    const float* ew    = (const float*)d_in[14];
    const float* eb    = (const float*)d_in[15];
    const float* vvec  = (const float*)d_in[16];
    const float* xw    = (const float*)d_in[17];
    const float* xb    = (const float*)d_in[18];
    const float* aw    = (const float*)d_in[19];
    const float* ab    = (const float*)d_in[20];
    const float* vw    = (const float*)d_in[21];
    const float* vb    = (const float*)d_in[22];
    const float* pw    = (const float*)d_in[23];
    const float* pb    = (const float*)d_in[24];
    float* out = (float*)d_out;

    float *cbuf0, *cbuf1, *xbuf0, *xbuf1;
    cudaGetSymbolAddress((void**)&cbuf0, g_c2);  cbuf1 = cbuf0 + Bz*Hz;
    cudaGetSymbolAddress((void**)&xbuf0, g_x2);  xbuf1 = xbuf0 + Bz*Ez;

    // Precompute phase
    k_init<<<32, 512>>>(h0, c0, ctx0, cov0);
    k_zero<<<(Bz*Tz*VEz/4 + 255)/256, 256>>>(out);
    k_transpose<<<dim3((Vz+31)/32, Hz/32), dim3(32, 8)>>>(vw);
    k_encproj<<<dim3((Bz*Sz)/128, Hz/64), 256>>>(enc, ew, eb);
    k_x0<<<32, 256>>>(emb, xw, xb);

    for (int t = 0; t < Tz; t++){
        const float* xc = (t & 1) ? xbuf1 : xbuf0;
        float*       xn = (t & 1) ? xbuf0 : xbuf1;
        const float* ci = (t & 1) ? cbuf1 : cbuf0;
        float*       co = (t & 1) ? cbuf0 : cbuf1;
        k_gates<<<(4*Hz)/8, 256>>>(Wih, Whh, bih, bhh, xc);
        k_lstmhp<<<dim3(4, Bz), 512>>>(ew, ci, co);
        k_energy<<<dim3(Sz/8, Bz), 256>>>(covw, vvec);
        k_attn<<<Bz, 512>>>(mask, out + OUT_ATTN, out + OUT_COV, t);
        k_ctx<<<dim3(8, Bz), 512>>>(enc);
        k_attnd<<<136, 256>>>(aw, ab, pw, pb, xw, xb, emb, xc, xn, out + OUT_PGEN, t);
        k_vocab<<<(Vz + 255)/256, 256>>>(vb);
        k_vsoftmax<<<Bz, 1024>>>();
        k_finalsc<<<dim3(197, Bz), 256>>>(out, sidx, t);
    }
    k_fin<<<16, 256>>>(out);
}